// round 5
// baseline (speedup 1.0000x reference)
#include <cuda_runtime.h>
#include <cuda_bf16.h>
#include <stdint.h>

#define M_ROWS   8192
#define DM       768
#define NF       16384
#define TOPK     64
#define TOPC     128         // candidates for exact rescore
#define KEFF     2304        // 3 * 768 (hi|hi|lo  x  hi|lo|hi)

// ---------------- scratch (__device__ globals; no allocs) ----------------
__device__ __align__(256) __nv_bfloat16 g_A[M_ROWS * KEFF];  // 37.7 MB [hi|hi|lo]
__device__ __align__(256) __nv_bfloat16 g_B[NF     * KEFF];  // 75.5 MB [hi|lo|hi]
__device__ int   g_cand[M_ROWS * TOPC];
__device__ int   g_tki [M_ROWS * TOPK];
__device__ float g_tkv [M_ROWS * TOPK];

// ---------------- helpers ----------------
__device__ __forceinline__ uint32_t smem_u32(const void* p) {
    uint32_t a;
    asm("{ .reg .u64 t; cvta.to.shared.u64 t, %1; cvt.u32.u64 %0, t; }" : "=r"(a) : "l"(p));
    return a;
}
__device__ __forceinline__ void cp_async16(uint32_t dst, const void* src) {
    asm volatile("cp.async.cg.shared.global [%0], [%1], 16;" :: "r"(dst), "l"(src));
}
#define CP_COMMIT() asm volatile("cp.async.commit_group;" ::: "memory")
#define CP_WAIT(n)  asm volatile("cp.async.wait_group %0;" :: "n"(n) : "memory")

__device__ __forceinline__ void mma16816(float* c,
                                         uint32_t a0, uint32_t a1, uint32_t a2, uint32_t a3,
                                         uint32_t b0, uint32_t b1) {
    asm volatile("mma.sync.aligned.m16n8k16.row.col.f32.bf16.bf16.f32 "
        "{%0,%1,%2,%3}, {%4,%5,%6,%7}, {%8,%9}, {%0,%1,%2,%3};"
        : "+f"(c[0]), "+f"(c[1]), "+f"(c[2]), "+f"(c[3])
        : "r"(a0), "r"(a1), "r"(a2), "r"(a3), "r"(b0), "r"(b1));
}

// ============================================================
// convert: fp32 -> (hi, lo) bf16 splits, K-concatenated
// ============================================================
__global__ void convert_x_kernel(const float* __restrict__ x) {
    int i = blockIdx.x * blockDim.x + threadIdx.x;
    if (i >= M_ROWS * DM) return;
    int r = i / DM, k = i % DM;
    float v = x[i];
    __nv_bfloat16 hi = __float2bfloat16(v);
    __nv_bfloat16 lo = __float2bfloat16(v - __bfloat162float(hi));
    size_t base = (size_t)r * KEFF + k;
    g_A[base]          = hi;
    g_A[base + DM]     = hi;
    g_A[base + 2 * DM] = lo;
}
__global__ void convert_w_kernel(const float* __restrict__ w) {
    int i = blockIdx.x * blockDim.x + threadIdx.x;
    if (i >= NF * DM) return;
    int r = i / DM, k = i % DM;
    float v = w[i];
    __nv_bfloat16 hi = __float2bfloat16(v);
    __nv_bfloat16 lo = __float2bfloat16(v - __bfloat162float(hi));
    size_t base = (size_t)r * KEFF + k;
    g_B[base]          = hi;
    g_B[base + DM]     = lo;
    g_B[base + 2 * DM] = hi;
}

// ============================================================
// zero codes
// ============================================================
__global__ void zero_kernel(float4* __restrict__ p, size_t n4) {
    size_t i = (size_t)blockIdx.x * blockDim.x + threadIdx.x;
    size_t stride = (size_t)gridDim.x * blockDim.x;
    float4 z = make_float4(0.f, 0.f, 0.f, 0.f);
    for (; i < n4; i += stride) p[i] = z;
}

// ============================================================
// mma.sync bf16 GEMM with WATERTIGHT 2-stage double buffer:
//   issue(kb+1); commit; wait_group(1); sync; compute(kb); sync;
// Every buffer provably quiescent before reuse.
// ============================================================
#define BM 128
#define BN 128
#define BK 32
#define ROWB 80                        // 64B data + 16B pad
#define STG (256 * ROWB)               // A(128 rows) + B(128 rows) = 20480 B
#define GEMM_SMEM (2 * STG)            // 40960 B
#define KITERS (KEFF / BK)             // 72

__global__ __launch_bounds__(256, 2)
void gemm_mma_kernel(const float* __restrict__ bias, float* __restrict__ pre) {
    extern __shared__ char sm[];
    const uint32_t sb = smem_u32(sm);
    const int tid = threadIdx.x;
    const int wid = tid >> 5;
    const int lane = tid & 31;
    const int g   = lane >> 2;      // 0..7
    const int tig = lane & 3;       // 0..3
    const int bm = blockIdx.x * BM;
    const int bn = blockIdx.y * BN;
    const int wm = (wid >> 2) * 64;
    const int wn = (wid & 3) * 32;

    const __nv_bfloat16* Ag = g_A + (size_t)bm * KEFF;
    const __nv_bfloat16* Bg = g_B + (size_t)bn * KEFF;

    float acc[4][4][4];
#pragma unroll
    for (int mi = 0; mi < 4; mi++)
#pragma unroll
        for (int ni = 0; ni < 4; ni++)
#pragma unroll
            for (int q = 0; q < 4; q++) acc[mi][ni][q] = 0.f;

    const int lr0 = tid >> 2;              // 0..63
    const int lr1 = (tid + 256) >> 2;      // 64..127
    const int lc  = tid & 3;               // 0..3

    auto issue = [&](int s) {
        const uint32_t base = sb + (s & 1) * STG;
        const size_t k0 = (size_t)s * BK;
        cp_async16(base + lr0 * ROWB + lc * 16, Ag + (size_t)lr0 * KEFF + k0 + lc * 8);
        cp_async16(base + lr1 * ROWB + lc * 16, Ag + (size_t)lr1 * KEFF + k0 + lc * 8);
        const uint32_t bb = base + 128 * ROWB;
        cp_async16(bb + lr0 * ROWB + lc * 16, Bg + (size_t)lr0 * KEFF + k0 + lc * 8);
        cp_async16(bb + lr1 * ROWB + lc * 16, Bg + (size_t)lr1 * KEFF + k0 + lc * 8);
    };

    issue(0);
    CP_COMMIT();

    for (int kb = 0; kb < KITERS; kb++) {
        if (kb + 1 < KITERS) issue(kb + 1);
        CP_COMMIT();
        CP_WAIT(1);          // stage kb complete; stage kb+1 may be in flight
        __syncthreads();

        const char* Abuf = sm + (kb & 1) * STG;
        const char* Bbuf = Abuf + 128 * ROWB;
#pragma unroll
        for (int kk = 0; kk < 2; kk++) {
            uint32_t bfr[4][2];
#pragma unroll
            for (int ni = 0; ni < 4; ni++) {
                const char* bp = Bbuf + (wn + ni * 8 + g) * ROWB + kk * 32 + tig * 4;
                bfr[ni][0] = *(const uint32_t*)bp;
                bfr[ni][1] = *(const uint32_t*)(bp + 16);
            }
#pragma unroll
            for (int mi = 0; mi < 4; mi++) {
                const char* ap0 = Abuf + (wm + mi * 16 + g) * ROWB + kk * 32 + tig * 4;
                const char* ap1 = ap0 + 8 * ROWB;
                uint32_t a0 = *(const uint32_t*)ap0;
                uint32_t a1 = *(const uint32_t*)ap1;
                uint32_t a2 = *(const uint32_t*)(ap0 + 16);
                uint32_t a3 = *(const uint32_t*)(ap1 + 16);
#pragma unroll
                for (int ni = 0; ni < 4; ni++)
                    mma16816(acc[mi][ni], a0, a1, a2, a3, bfr[ni][0], bfr[ni][1]);
            }
        }
        __syncthreads();     // buffer (kb&1) fully consumed before reuse at kb+2
    }

    // epilogue: add bias, store fp32
#pragma unroll
    for (int ni = 0; ni < 4; ni++) {
        const int col = bn + wn + ni * 8 + tig * 2;
        float2 bz = *(const float2*)(bias + col);
#pragma unroll
        for (int mi = 0; mi < 4; mi++) {
            const int r0 = bm + wm + mi * 16 + g;
            float2 v0, v1;
            v0.x = acc[mi][ni][0] + bz.x; v0.y = acc[mi][ni][1] + bz.y;
            v1.x = acc[mi][ni][2] + bz.x; v1.y = acc[mi][ni][3] + bz.y;
            *(float2*)(pre + (size_t)r0 * NF + col)       = v0;
            *(float2*)(pre + (size_t)(r0 + 8) * NF + col) = v1;
        }
    }
}

// ============================================================
// top-128 candidate select (radix on ordered uints, approx pre)
// ============================================================
__global__ __launch_bounds__(256)
void topc_kernel(const float* __restrict__ pre) {
    extern __shared__ unsigned su[];             // NF keys (64 KB)
    __shared__ unsigned hist[256];
    __shared__ unsigned s_prefix, s_want;
    __shared__ unsigned cnt;

    const int row = blockIdx.x;
    const int tid = threadIdx.x;
    const float* p = pre + (size_t)row * NF;

    for (int i = tid; i < NF; i += 256) {
        unsigned b = __float_as_uint(p[i]);
        su[i] = (b & 0x80000000u) ? ~b : (b | 0x80000000u);
    }
    if (tid == 0) { s_prefix = 0u; s_want = TOPC; cnt = 0u; }
    __syncthreads();

#pragma unroll
    for (int shift = 24; shift >= 0; shift -= 8) {
        hist[tid] = 0u;
        __syncthreads();
        unsigned pref = s_prefix;
        for (int i = tid; i < NF; i += 256) {
            unsigned u = su[i];
            bool match = (shift == 24) || ((u >> (shift + 8)) == pref);
            if (match) atomicAdd(&hist[(u >> shift) & 255u], 1u);
        }
        __syncthreads();
        if (tid == 0) {
            unsigned want = s_want, cum = 0;
            for (int b = 255; b >= 0; b--) {
                unsigned c = hist[b];
                if (cum + c >= want) { s_prefix = (pref << 8) | (unsigned)b; s_want = want - cum; break; }
                cum += c;
            }
        }
        __syncthreads();
    }

    const unsigned pivot = s_prefix;
    const int base = row * TOPC;
    for (int i = tid; i < NF; i += 256) {
        if (su[i] >= pivot) {
            unsigned slot = atomicAdd(&cnt, 1u);
            if (slot < TOPC) g_cand[base + slot] = i;
        }
    }
}

// ============================================================
// exact rescore of 128 candidates, round-1-identical fp32:
// sequential ascending-k FFMA chain per candidate, + bias FADD.
// 4 batches x 32 candidates, W rows staged in smem stride 769.
// ============================================================
#define RS_BATCH   32
#define RS_STRIDE  769                               // 768 + 1 pad
#define RS_WS_OFF  DM
#define RS_FLOATS  (DM + RS_BATCH * RS_STRIDE)
#define RS_SMEM    (RS_FLOATS * 4)                   // 101,504 B

__global__ __launch_bounds__(256, 2)
void rescore_kernel(const float* __restrict__ x,
                    const float* __restrict__ Wenc,
                    const float* __restrict__ benc,
                    float* __restrict__ codes) {
    extern __shared__ float sf[];                    // xs[768] | ws[32][769]
    __shared__ float sval[TOPC];
    __shared__ int   sidx[TOPC];
    __shared__ int   bcand[RS_BATCH];

    const int row = blockIdx.x;
    const int tid = threadIdx.x;

    for (int i = tid; i < DM; i += 256) sf[i] = x[(size_t)row * DM + i];

    for (int b = 0; b < TOPC / RS_BATCH; b++) {
        const int cbase = b * RS_BATCH;
        __syncthreads();
        if (tid < RS_BATCH) bcand[tid] = g_cand[row * TOPC + cbase + tid];
        __syncthreads();

        for (int i = tid; i < RS_BATCH * DM; i += 256) {
            int r = i / DM, k = i - r * DM;
            sf[RS_WS_OFF + r * RS_STRIDE + k] = Wenc[(size_t)bcand[r] * DM + k];
        }
        __syncthreads();

        if (tid < RS_BATCH) {
            const float* wr = sf + RS_WS_OFF + tid * RS_STRIDE;
            float acc = 0.f;
            #pragma unroll 16
            for (int k = 0; k < DM; k++)
                acc = fmaf(sf[k], wr[k], acc);       // ascending-k FFMA chain
            int idx = bcand[tid];
            sval[cbase + tid] = acc + benc[idx];
            sidx[cbase + tid] = idx;
        }
    }
    __syncthreads();

    if (tid < TOPC) {
        float v = sval[tid];
        int myi = sidx[tid];
        int rank = 0;
        #pragma unroll 8
        for (int j = 0; j < TOPC; j++) {
            float vj = sval[j];
            rank += (vj > v) || (vj == v && sidx[j] < myi);
        }
        if (rank < TOPK) {
            g_tki[row * TOPK + rank] = myi;
            g_tkv[row * TOPK + rank] = v;
            codes[(size_t)row * NF + myi] = v;
        }
    }
}

// ============================================================
// sparse decode
// ============================================================
__global__ __launch_bounds__(256)
void decode_kernel(const float* __restrict__ Dm, float* __restrict__ recon) {
    __shared__ int   sidx[TOPK];
    __shared__ float sval[TOPK];
    const int row = blockIdx.x;
    const int tid = threadIdx.x;
    if (tid < TOPK) {
        sidx[tid] = g_tki[row * TOPK + tid];
        sval[tid] = g_tkv[row * TOPK + tid];
    }
    __syncthreads();
    const int c0 = tid, c1 = tid + 256, c2 = tid + 512;
    float a0 = 0.f, a1 = 0.f, a2 = 0.f;
#pragma unroll 4
    for (int k = 0; k < TOPK; k++) {
        const float* dr = Dm + (size_t)sidx[k] * DM;
        float v = sval[k];
        a0 += v * dr[c0]; a1 += v * dr[c1]; a2 += v * dr[c2];
    }
    float* r = recon + (size_t)row * DM;
    r[c0] = a0; r[c1] = a1; r[c2] = a2;
}

// ============================================================
// launch
// ============================================================
extern "C" void kernel_launch(void* const* d_in, const int* in_sizes, int n_in,
                              void* d_out, int out_size) {
    const float* x    = (const float*)d_in[0];
    const float* Wenc = (const float*)d_in[1];
    const float* benc = (const float*)d_in[2];
    const float* Dm   = (const float*)d_in[3];

    float* out   = (float*)d_out;
    float* recon = out;
    float* codes = out + (size_t)M_ROWS * DM;
    float* pre   = codes + (size_t)M_ROWS * NF;

    cudaFuncSetAttribute(gemm_mma_kernel,
                         cudaFuncAttributeMaxDynamicSharedMemorySize, GEMM_SMEM);
    cudaFuncSetAttribute(topc_kernel,
                         cudaFuncAttributeMaxDynamicSharedMemorySize,
                         NF * (int)sizeof(unsigned));
    cudaFuncSetAttribute(rescore_kernel,
                         cudaFuncAttributeMaxDynamicSharedMemorySize, RS_SMEM);

    // 1) convert inputs to split-bf16 concatenated layouts
    convert_x_kernel<<<(M_ROWS * DM + 255) / 256, 256>>>(x);
    convert_w_kernel<<<(NF * DM + 255) / 256, 256>>>(Wenc);
    // 2) zero codes
    zero_kernel<<<16384, 256>>>((float4*)codes, (size_t)M_ROWS * NF / 4);
    // 3) tensor-core encode GEMM -> pre (+bias)
    {
        dim3 grid(M_ROWS / BM, NF / BN);
        gemm_mma_kernel<<<grid, 256, GEMM_SMEM>>>(benc, pre);
    }
    // 4) approx top-128 candidates
    topc_kernel<<<M_ROWS, 256, NF * sizeof(unsigned)>>>(pre);
    // 5) exact rescore (round-1-identical arithmetic) -> top-64, scatter
    rescore_kernel<<<M_ROWS, 256, RS_SMEM>>>(x, Wenc, benc, codes);
    // 6) sparse decode
    decode_kernel<<<M_ROWS, 256>>>(Dm, recon);
}

// round 6
// speedup vs baseline: 1.0001x; 1.0001x over previous
#include <cuda_runtime.h>
#include <cuda_bf16.h>
#include <stdint.h>

#define M_ROWS   8192
#define DM       768
#define NF       16384
#define TOPK     64
#define TOPC     128         // candidates for exact rescore
#define KEFF     2304        // 3 * 768 (hi|hi|lo  x  hi|lo|hi)

// ---------------- scratch (__device__ globals; no allocs) ----------------
__device__ __align__(256) __nv_bfloat16 g_A[M_ROWS * KEFF];  // 37.7 MB [hi|hi|lo]
__device__ __align__(256) __nv_bfloat16 g_B[NF     * KEFF];  // 75.5 MB [hi|lo|hi]
__device__ int   g_cand[M_ROWS * TOPC];
__device__ int   g_tki [M_ROWS * TOPK];
__device__ float g_tkv [M_ROWS * TOPK];

// ---------------- helpers ----------------
__device__ __forceinline__ uint32_t smem_u32(const void* p) {
    uint32_t a;
    asm("{ .reg .u64 t; cvta.to.shared.u64 t, %1; cvt.u32.u64 %0, t; }" : "=r"(a) : "l"(p));
    return a;
}
__device__ __forceinline__ void cp_async16(uint32_t dst, const void* src) {
    asm volatile("cp.async.cg.shared.global [%0], [%1], 16;" :: "r"(dst), "l"(src));
}
#define CP_COMMIT() asm volatile("cp.async.commit_group;" ::: "memory")
#define CP_WAIT(n)  asm volatile("cp.async.wait_group %0;" :: "n"(n) : "memory")

__device__ __forceinline__ void mma16816(float* c,
                                         uint32_t a0, uint32_t a1, uint32_t a2, uint32_t a3,
                                         uint32_t b0, uint32_t b1) {
    asm volatile("mma.sync.aligned.m16n8k16.row.col.f32.bf16.bf16.f32 "
        "{%0,%1,%2,%3}, {%4,%5,%6,%7}, {%8,%9}, {%0,%1,%2,%3};"
        : "+f"(c[0]), "+f"(c[1]), "+f"(c[2]), "+f"(c[3])
        : "r"(a0), "r"(a1), "r"(a2), "r"(a3), "r"(b0), "r"(b1));
}

// ============================================================
// convert: fp32 -> (hi, lo) bf16 splits, K-concatenated
// ============================================================
__global__ void convert_x_kernel(const float* __restrict__ x) {
    int i = blockIdx.x * blockDim.x + threadIdx.x;
    if (i >= M_ROWS * DM) return;
    int r = i / DM, k = i % DM;
    float v = x[i];
    __nv_bfloat16 hi = __float2bfloat16(v);
    __nv_bfloat16 lo = __float2bfloat16(v - __bfloat162float(hi));
    size_t base = (size_t)r * KEFF + k;
    g_A[base]          = hi;
    g_A[base + DM]     = hi;
    g_A[base + 2 * DM] = lo;
}
__global__ void convert_w_kernel(const float* __restrict__ w) {
    int i = blockIdx.x * blockDim.x + threadIdx.x;
    if (i >= NF * DM) return;
    int r = i / DM, k = i % DM;
    float v = w[i];
    __nv_bfloat16 hi = __float2bfloat16(v);
    __nv_bfloat16 lo = __float2bfloat16(v - __bfloat162float(hi));
    size_t base = (size_t)r * KEFF + k;
    g_B[base]          = hi;
    g_B[base + DM]     = lo;
    g_B[base + 2 * DM] = hi;
}

// ============================================================
// zero codes
// ============================================================
__global__ void zero_kernel(float4* __restrict__ p, size_t n4) {
    size_t i = (size_t)blockIdx.x * blockDim.x + threadIdx.x;
    size_t stride = (size_t)gridDim.x * blockDim.x;
    float4 z = make_float4(0.f, 0.f, 0.f, 0.f);
    for (; i < n4; i += stride) p[i] = z;
}

// ============================================================
// mma.sync bf16 GEMM with WATERTIGHT 2-stage double buffer:
//   issue(kb+1); commit; wait_group(1); sync; compute(kb); sync;
// Every buffer provably quiescent before reuse.
// ============================================================
#define BM 128
#define BN 128
#define BK 32
#define ROWB 80                        // 64B data + 16B pad
#define STG (256 * ROWB)               // A(128 rows) + B(128 rows) = 20480 B
#define GEMM_SMEM (2 * STG)            // 40960 B
#define KITERS (KEFF / BK)             // 72

__global__ __launch_bounds__(256, 2)
void gemm_mma_kernel(const float* __restrict__ bias, float* __restrict__ pre) {
    extern __shared__ char sm[];
    const uint32_t sb = smem_u32(sm);
    const int tid = threadIdx.x;
    const int wid = tid >> 5;
    const int lane = tid & 31;
    const int g   = lane >> 2;      // 0..7
    const int tig = lane & 3;       // 0..3
    const int bm = blockIdx.x * BM;
    const int bn = blockIdx.y * BN;
    const int wm = (wid >> 2) * 64;
    const int wn = (wid & 3) * 32;

    const __nv_bfloat16* Ag = g_A + (size_t)bm * KEFF;
    const __nv_bfloat16* Bg = g_B + (size_t)bn * KEFF;

    float acc[4][4][4];
#pragma unroll
    for (int mi = 0; mi < 4; mi++)
#pragma unroll
        for (int ni = 0; ni < 4; ni++)
#pragma unroll
            for (int q = 0; q < 4; q++) acc[mi][ni][q] = 0.f;

    const int lr0 = tid >> 2;              // 0..63
    const int lr1 = (tid + 256) >> 2;      // 64..127
    const int lc  = tid & 3;               // 0..3

    auto issue = [&](int s) {
        const uint32_t base = sb + (s & 1) * STG;
        const size_t k0 = (size_t)s * BK;
        cp_async16(base + lr0 * ROWB + lc * 16, Ag + (size_t)lr0 * KEFF + k0 + lc * 8);
        cp_async16(base + lr1 * ROWB + lc * 16, Ag + (size_t)lr1 * KEFF + k0 + lc * 8);
        const uint32_t bb = base + 128 * ROWB;
        cp_async16(bb + lr0 * ROWB + lc * 16, Bg + (size_t)lr0 * KEFF + k0 + lc * 8);
        cp_async16(bb + lr1 * ROWB + lc * 16, Bg + (size_t)lr1 * KEFF + k0 + lc * 8);
    };

    issue(0);
    CP_COMMIT();

    for (int kb = 0; kb < KITERS; kb++) {
        if (kb + 1 < KITERS) issue(kb + 1);
        CP_COMMIT();
        CP_WAIT(1);          // stage kb complete; stage kb+1 may be in flight
        __syncthreads();

        const char* Abuf = sm + (kb & 1) * STG;
        const char* Bbuf = Abuf + 128 * ROWB;
#pragma unroll
        for (int kk = 0; kk < 2; kk++) {
            uint32_t bfr[4][2];
#pragma unroll
            for (int ni = 0; ni < 4; ni++) {
                const char* bp = Bbuf + (wn + ni * 8 + g) * ROWB + kk * 32 + tig * 4;
                bfr[ni][0] = *(const uint32_t*)bp;
                bfr[ni][1] = *(const uint32_t*)(bp + 16);
            }
#pragma unroll
            for (int mi = 0; mi < 4; mi++) {
                const char* ap0 = Abuf + (wm + mi * 16 + g) * ROWB + kk * 32 + tig * 4;
                const char* ap1 = ap0 + 8 * ROWB;
                uint32_t a0 = *(const uint32_t*)ap0;
                uint32_t a1 = *(const uint32_t*)ap1;
                uint32_t a2 = *(const uint32_t*)(ap0 + 16);
                uint32_t a3 = *(const uint32_t*)(ap1 + 16);
#pragma unroll
                for (int ni = 0; ni < 4; ni++)
                    mma16816(acc[mi][ni], a0, a1, a2, a3, bfr[ni][0], bfr[ni][1]);
            }
        }
        __syncthreads();     // buffer (kb&1) fully consumed before reuse at kb+2
    }

    // epilogue: add bias, store fp32
#pragma unroll
    for (int ni = 0; ni < 4; ni++) {
        const int col = bn + wn + ni * 8 + tig * 2;
        float2 bz = *(const float2*)(bias + col);
#pragma unroll
        for (int mi = 0; mi < 4; mi++) {
            const int r0 = bm + wm + mi * 16 + g;
            float2 v0, v1;
            v0.x = acc[mi][ni][0] + bz.x; v0.y = acc[mi][ni][1] + bz.y;
            v1.x = acc[mi][ni][2] + bz.x; v1.y = acc[mi][ni][3] + bz.y;
            *(float2*)(pre + (size_t)r0 * NF + col)       = v0;
            *(float2*)(pre + (size_t)(r0 + 8) * NF + col) = v1;
        }
    }
}

// ============================================================
// top-128 candidate select (radix on ordered uints, approx pre)
// ============================================================
__global__ __launch_bounds__(256)
void topc_kernel(const float* __restrict__ pre) {
    extern __shared__ unsigned su[];             // NF keys (64 KB)
    __shared__ unsigned hist[256];
    __shared__ unsigned s_prefix, s_want;
    __shared__ unsigned cnt;

    const int row = blockIdx.x;
    const int tid = threadIdx.x;
    const float* p = pre + (size_t)row * NF;

    for (int i = tid; i < NF; i += 256) {
        unsigned b = __float_as_uint(p[i]);
        su[i] = (b & 0x80000000u) ? ~b : (b | 0x80000000u);
    }
    if (tid == 0) { s_prefix = 0u; s_want = TOPC; cnt = 0u; }
    __syncthreads();

#pragma unroll
    for (int shift = 24; shift >= 0; shift -= 8) {
        hist[tid] = 0u;
        __syncthreads();
        unsigned pref = s_prefix;
        for (int i = tid; i < NF; i += 256) {
            unsigned u = su[i];
            bool match = (shift == 24) || ((u >> (shift + 8)) == pref);
            if (match) atomicAdd(&hist[(u >> shift) & 255u], 1u);
        }
        __syncthreads();
        if (tid == 0) {
            unsigned want = s_want, cum = 0;
            for (int b = 255; b >= 0; b--) {
                unsigned c = hist[b];
                if (cum + c >= want) { s_prefix = (pref << 8) | (unsigned)b; s_want = want - cum; break; }
                cum += c;
            }
        }
        __syncthreads();
    }

    const unsigned pivot = s_prefix;
    const int base = row * TOPC;
    for (int i = tid; i < NF; i += 256) {
        if (su[i] >= pivot) {
            unsigned slot = atomicAdd(&cnt, 1u);
            if (slot < TOPC) g_cand[base + slot] = i;
        }
    }
}

// ============================================================
// exact rescore of 128 candidates, round-1-identical fp32:
// sequential ascending-k FFMA chain per candidate, + bias FADD.
// 4 batches x 32 candidates, W rows staged in smem stride 769.
// ============================================================
#define RS_BATCH   32
#define RS_STRIDE  769                               // 768 + 1 pad
#define RS_WS_OFF  DM
#define RS_FLOATS  (DM + RS_BATCH * RS_STRIDE)
#define RS_SMEM    (RS_FLOATS * 4)                   // 101,504 B

__global__ __launch_bounds__(256, 2)
void rescore_kernel(const float* __restrict__ x,
                    const float* __restrict__ Wenc,
                    const float* __restrict__ benc,
                    float* __restrict__ codes) {
    extern __shared__ float sf[];                    // xs[768] | ws[32][769]
    __shared__ float sval[TOPC];
    __shared__ int   sidx[TOPC];
    __shared__ int   bcand[RS_BATCH];

    const int row = blockIdx.x;
    const int tid = threadIdx.x;

    for (int i = tid; i < DM; i += 256) sf[i] = x[(size_t)row * DM + i];

    for (int b = 0; b < TOPC / RS_BATCH; b++) {
        const int cbase = b * RS_BATCH;
        __syncthreads();
        if (tid < RS_BATCH) bcand[tid] = g_cand[row * TOPC + cbase + tid];
        __syncthreads();

        for (int i = tid; i < RS_BATCH * DM; i += 256) {
            int r = i / DM, k = i - r * DM;
            sf[RS_WS_OFF + r * RS_STRIDE + k] = Wenc[(size_t)bcand[r] * DM + k];
        }
        __syncthreads();

        if (tid < RS_BATCH) {
            const float* wr = sf + RS_WS_OFF + tid * RS_STRIDE;
            float acc = 0.f;
            #pragma unroll 16
            for (int k = 0; k < DM; k++)
                acc = fmaf(sf[k], wr[k], acc);       // ascending-k FFMA chain
            int idx = bcand[tid];
            sval[cbase + tid] = acc + benc[idx];
            sidx[cbase + tid] = idx;
        }
    }
    __syncthreads();

    if (tid < TOPC) {
        float v = sval[tid];
        int myi = sidx[tid];
        int rank = 0;
        #pragma unroll 8
        for (int j = 0; j < TOPC; j++) {
            float vj = sval[j];
            rank += (vj > v) || (vj == v && sidx[j] < myi);
        }
        if (rank < TOPK) {
            g_tki[row * TOPK + rank] = myi;
            g_tkv[row * TOPK + rank] = v;
            codes[(size_t)row * NF + myi] = v;
        }
    }
}

// ============================================================
// sparse decode
// ============================================================
__global__ __launch_bounds__(256)
void decode_kernel(const float* __restrict__ Dm, float* __restrict__ recon) {
    __shared__ int   sidx[TOPK];
    __shared__ float sval[TOPK];
    const int row = blockIdx.x;
    const int tid = threadIdx.x;
    if (tid < TOPK) {
        sidx[tid] = g_tki[row * TOPK + tid];
        sval[tid] = g_tkv[row * TOPK + tid];
    }
    __syncthreads();
    const int c0 = tid, c1 = tid + 256, c2 = tid + 512;
    float a0 = 0.f, a1 = 0.f, a2 = 0.f;
#pragma unroll 4
    for (int k = 0; k < TOPK; k++) {
        const float* dr = Dm + (size_t)sidx[k] * DM;
        float v = sval[k];
        a0 += v * dr[c0]; a1 += v * dr[c1]; a2 += v * dr[c2];
    }
    float* r = recon + (size_t)row * DM;
    r[c0] = a0; r[c1] = a1; r[c2] = a2;
}

// ============================================================
// launch
// ============================================================
extern "C" void kernel_launch(void* const* d_in, const int* in_sizes, int n_in,
                              void* d_out, int out_size) {
    const float* x    = (const float*)d_in[0];
    const float* Wenc = (const float*)d_in[1];
    const float* benc = (const float*)d_in[2];
    const float* Dm   = (const float*)d_in[3];

    float* out   = (float*)d_out;
    float* recon = out;
    float* codes = out + (size_t)M_ROWS * DM;
    float* pre   = codes + (size_t)M_ROWS * NF;

    cudaFuncSetAttribute(gemm_mma_kernel,
                         cudaFuncAttributeMaxDynamicSharedMemorySize, GEMM_SMEM);
    cudaFuncSetAttribute(topc_kernel,
                         cudaFuncAttributeMaxDynamicSharedMemorySize,
                         NF * (int)sizeof(unsigned));
    cudaFuncSetAttribute(rescore_kernel,
                         cudaFuncAttributeMaxDynamicSharedMemorySize, RS_SMEM);

    // 1) convert inputs to split-bf16 concatenated layouts
    convert_x_kernel<<<(M_ROWS * DM + 255) / 256, 256>>>(x);
    convert_w_kernel<<<(NF * DM + 255) / 256, 256>>>(Wenc);
    // 2) zero codes
    zero_kernel<<<16384, 256>>>((float4*)codes, (size_t)M_ROWS * NF / 4);
    // 3) tensor-core encode GEMM -> pre (+bias)
    {
        dim3 grid(M_ROWS / BM, NF / BN);
        gemm_mma_kernel<<<grid, 256, GEMM_SMEM>>>(benc, pre);
    }
    // 4) approx top-128 candidates
    topc_kernel<<<M_ROWS, 256, NF * sizeof(unsigned)>>>(pre);
    // 5) exact rescore (round-1-identical arithmetic) -> top-64, scatter
    rescore_kernel<<<M_ROWS, 256, RS_SMEM>>>(x, Wenc, benc, codes);
    // 6) sparse decode
    decode_kernel<<<M_ROWS, 256>>>(Dm, recon);
}

// round 7
// speedup vs baseline: 1.3111x; 1.3109x over previous
#include <cuda_runtime.h>
#include <cuda_fp16.h>
#include <stdint.h>

#define M_ROWS   8192
#define DM       768
#define NF       16384
#define TOPK     64
#define TOPC     128         // candidates for exact rescore
#define KDIM     768         // single-pass fp16 GEMM K

// ---------------- scratch (__device__ globals; no allocs) ----------------
__device__ __align__(256) __half g_A[M_ROWS * KDIM];   // 12.6 MB
__device__ __align__(256) __half g_B[NF     * KDIM];   // 25.2 MB
__device__ int   g_cand[M_ROWS * TOPC];
__device__ int   g_tki [M_ROWS * TOPK];
__device__ float g_tkv [M_ROWS * TOPK];

// ---------------- helpers ----------------
__device__ __forceinline__ uint32_t smem_u32(const void* p) {
    uint32_t a;
    asm("{ .reg .u64 t; cvta.to.shared.u64 t, %1; cvt.u32.u64 %0, t; }" : "=r"(a) : "l"(p));
    return a;
}
__device__ __forceinline__ void cp_async16(uint32_t dst, const void* src) {
    asm volatile("cp.async.cg.shared.global [%0], [%1], 16;" :: "r"(dst), "l"(src));
}
#define CP_COMMIT() asm volatile("cp.async.commit_group;" ::: "memory")
#define CP_WAIT(n)  asm volatile("cp.async.wait_group %0;" :: "n"(n) : "memory")

__device__ __forceinline__ void mma16816(float* c,
                                         uint32_t a0, uint32_t a1, uint32_t a2, uint32_t a3,
                                         uint32_t b0, uint32_t b1) {
    asm volatile("mma.sync.aligned.m16n8k16.row.col.f32.f16.f16.f32 "
        "{%0,%1,%2,%3}, {%4,%5,%6,%7}, {%8,%9}, {%0,%1,%2,%3};"
        : "+f"(c[0]), "+f"(c[1]), "+f"(c[2]), "+f"(c[3])
        : "r"(a0), "r"(a1), "r"(a2), "r"(a3), "r"(b0), "r"(b1));
}

// ============================================================
// convert: fp32 -> fp16 (single hi pass), vectorized x4
// ============================================================
__global__ void convert_x_kernel(const float* __restrict__ x) {
    int i = blockIdx.x * blockDim.x + threadIdx.x;      // quad index
    if (i >= M_ROWS * KDIM / 4) return;
    float4 v = ((const float4*)x)[i];
    __half2 h0 = __floats2half2_rn(v.x, v.y);
    __half2 h1 = __floats2half2_rn(v.z, v.w);
    ((__half2*)g_A)[i * 2]     = h0;
    ((__half2*)g_A)[i * 2 + 1] = h1;
}
__global__ void convert_w_kernel(const float* __restrict__ w) {
    int i = blockIdx.x * blockDim.x + threadIdx.x;
    if (i >= NF * KDIM / 4) return;
    float4 v = ((const float4*)w)[i];
    __half2 h0 = __floats2half2_rn(v.x, v.y);
    __half2 h1 = __floats2half2_rn(v.z, v.w);
    ((__half2*)g_B)[i * 2]     = h0;
    ((__half2*)g_B)[i * 2 + 1] = h1;
}

// ============================================================
// zero codes
// ============================================================
__global__ void zero_kernel(float4* __restrict__ p, size_t n4) {
    size_t i = (size_t)blockIdx.x * blockDim.x + threadIdx.x;
    size_t stride = (size_t)gridDim.x * blockDim.x;
    float4 z = make_float4(0.f, 0.f, 0.f, 0.f);
    for (; i < n4; i += stride) p[i] = z;
}

// ============================================================
// mma.sync fp16 GEMM, watertight 3-stage pipeline:
//   issue(kb+2); commit; wait_group(2); sync; compute(kb); sync
// Group-count invariant: one commit per iteration, so after
// wait(2) group kb is complete; buffer (kb+2)%3 == (kb-1)%3 is
// reused only after the end-of-compute(kb-1) barrier.
// ============================================================
#define BM 128
#define BN 128
#define BK 32
#define STAGES 3
#define ROWB 80                        // 64B data (32 fp16) + 16B pad
#define STG (256 * ROWB)               // A(128) + B(128) rows = 20480 B
#define GEMM_SMEM (STAGES * STG)       // 61440 B
#define KITERS (KDIM / BK)             // 24

__global__ __launch_bounds__(256, 2)
void gemm_mma_kernel(const float* __restrict__ bias, float* __restrict__ pre) {
    extern __shared__ char sm[];
    const uint32_t sb = smem_u32(sm);
    const int tid = threadIdx.x;
    const int wid = tid >> 5;
    const int lane = tid & 31;
    const int g   = lane >> 2;      // 0..7
    const int tig = lane & 3;       // 0..3
    const int bm = blockIdx.x * BM;
    const int bn = blockIdx.y * BN;
    const int wm = (wid >> 2) * 64;
    const int wn = (wid & 3) * 32;

    const __half* Ag = g_A + (size_t)bm * KDIM;
    const __half* Bg = g_B + (size_t)bn * KDIM;

    float acc[4][4][4];
#pragma unroll
    for (int mi = 0; mi < 4; mi++)
#pragma unroll
        for (int ni = 0; ni < 4; ni++)
#pragma unroll
            for (int q = 0; q < 4; q++) acc[mi][ni][q] = 0.f;

    const int lr0 = tid >> 2;              // 0..63
    const int lr1 = (tid + 256) >> 2;      // 64..127
    const int lc  = tid & 3;               // 0..3

    auto issue = [&](int s) {
        const uint32_t base = sb + (s % STAGES) * STG;
        const size_t k0 = (size_t)s * BK;
        cp_async16(base + lr0 * ROWB + lc * 16, Ag + (size_t)lr0 * KDIM + k0 + lc * 8);
        cp_async16(base + lr1 * ROWB + lc * 16, Ag + (size_t)lr1 * KDIM + k0 + lc * 8);
        const uint32_t bb = base + 128 * ROWB;
        cp_async16(bb + lr0 * ROWB + lc * 16, Bg + (size_t)lr0 * KDIM + k0 + lc * 8);
        cp_async16(bb + lr1 * ROWB + lc * 16, Bg + (size_t)lr1 * KDIM + k0 + lc * 8);
    };

    issue(0); CP_COMMIT();
    issue(1); CP_COMMIT();

    for (int kb = 0; kb < KITERS; kb++) {
        if (kb + 2 < KITERS) issue(kb + 2);
        CP_COMMIT();                     // one group per iteration (may be empty)
        CP_WAIT(2);                      // group kb complete
        __syncthreads();

        const char* Abuf = sm + (kb % STAGES) * STG;
        const char* Bbuf = Abuf + 128 * ROWB;
#pragma unroll
        for (int kk = 0; kk < 2; kk++) {
            uint32_t bfr[4][2];
#pragma unroll
            for (int ni = 0; ni < 4; ni++) {
                const char* bp = Bbuf + (wn + ni * 8 + g) * ROWB + kk * 32 + tig * 4;
                bfr[ni][0] = *(const uint32_t*)bp;
                bfr[ni][1] = *(const uint32_t*)(bp + 16);
            }
#pragma unroll
            for (int mi = 0; mi < 4; mi++) {
                const char* ap0 = Abuf + (wm + mi * 16 + g) * ROWB + kk * 32 + tig * 4;
                const char* ap1 = ap0 + 8 * ROWB;
                uint32_t a0 = *(const uint32_t*)ap0;
                uint32_t a1 = *(const uint32_t*)ap1;
                uint32_t a2 = *(const uint32_t*)(ap0 + 16);
                uint32_t a3 = *(const uint32_t*)(ap1 + 16);
#pragma unroll
                for (int ni = 0; ni < 4; ni++)
                    mma16816(acc[mi][ni], a0, a1, a2, a3, bfr[ni][0], bfr[ni][1]);
            }
        }
        __syncthreads();                 // buffer kb%3 consumed before reuse
    }

    // epilogue: add bias, store fp32
#pragma unroll
    for (int ni = 0; ni < 4; ni++) {
        const int col = bn + wn + ni * 8 + tig * 2;
        float2 bz = *(const float2*)(bias + col);
#pragma unroll
        for (int mi = 0; mi < 4; mi++) {
            const int r0 = bm + wm + mi * 16 + g;
            float2 v0, v1;
            v0.x = acc[mi][ni][0] + bz.x; v0.y = acc[mi][ni][1] + bz.y;
            v1.x = acc[mi][ni][2] + bz.x; v1.y = acc[mi][ni][3] + bz.y;
            *(float2*)(pre + (size_t)r0 * NF + col)       = v0;
            *(float2*)(pre + (size_t)(r0 + 8) * NF + col) = v1;
        }
    }
}

// ============================================================
// top-128 candidate select (radix on ordered uints, approx pre)
// ============================================================
__global__ __launch_bounds__(256)
void topc_kernel(const float* __restrict__ pre) {
    extern __shared__ unsigned su[];             // NF keys (64 KB)
    __shared__ unsigned hist[256];
    __shared__ unsigned s_prefix, s_want;
    __shared__ unsigned cnt;

    const int row = blockIdx.x;
    const int tid = threadIdx.x;
    const float* p = pre + (size_t)row * NF;

    for (int i = tid; i < NF; i += 256) {
        unsigned b = __float_as_uint(p[i]);
        su[i] = (b & 0x80000000u) ? ~b : (b | 0x80000000u);
    }
    if (tid == 0) { s_prefix = 0u; s_want = TOPC; cnt = 0u; }
    __syncthreads();

#pragma unroll
    for (int shift = 24; shift >= 0; shift -= 8) {
        hist[tid] = 0u;
        __syncthreads();
        unsigned pref = s_prefix;
        for (int i = tid; i < NF; i += 256) {
            unsigned u = su[i];
            bool match = (shift == 24) || ((u >> (shift + 8)) == pref);
            if (match) atomicAdd(&hist[(u >> shift) & 255u], 1u);
        }
        __syncthreads();
        if (tid == 0) {
            unsigned want = s_want, cum = 0;
            for (int b = 255; b >= 0; b--) {
                unsigned c = hist[b];
                if (cum + c >= want) { s_prefix = (pref << 8) | (unsigned)b; s_want = want - cum; break; }
                cum += c;
            }
        }
        __syncthreads();
    }

    const unsigned pivot = s_prefix;
    const int base = row * TOPC;
    for (int i = tid; i < NF; i += 256) {
        if (su[i] >= pivot) {
            unsigned slot = atomicAdd(&cnt, 1u);
            if (slot < TOPC) g_cand[base + slot] = i;
        }
    }
}

// ============================================================
// exact rescore of 128 candidates (sequential ascending-k FFMA
// chain per candidate, + bias) -> exact top-64, scatter
// ============================================================
#define RS_BATCH   32
#define RS_STRIDE  769
#define RS_WS_OFF  DM
#define RS_FLOATS  (DM + RS_BATCH * RS_STRIDE)
#define RS_SMEM    (RS_FLOATS * 4)                   // 101,504 B

__global__ __launch_bounds__(256, 2)
void rescore_kernel(const float* __restrict__ x,
                    const float* __restrict__ Wenc,
                    const float* __restrict__ benc,
                    float* __restrict__ codes) {
    extern __shared__ float sf[];                    // xs[768] | ws[32][769]
    __shared__ float sval[TOPC];
    __shared__ int   sidx[TOPC];
    __shared__ int   bcand[RS_BATCH];

    const int row = blockIdx.x;
    const int tid = threadIdx.x;

    for (int i = tid; i < DM; i += 256) sf[i] = x[(size_t)row * DM + i];

    for (int b = 0; b < TOPC / RS_BATCH; b++) {
        const int cbase = b * RS_BATCH;
        __syncthreads();
        if (tid < RS_BATCH) bcand[tid] = g_cand[row * TOPC + cbase + tid];
        __syncthreads();

        for (int i = tid; i < RS_BATCH * DM; i += 256) {
            int r = i / DM, k = i - r * DM;
            sf[RS_WS_OFF + r * RS_STRIDE + k] = Wenc[(size_t)bcand[r] * DM + k];
        }
        __syncthreads();

        if (tid < RS_BATCH) {
            const float* wr = sf + RS_WS_OFF + tid * RS_STRIDE;
            float acc = 0.f;
            #pragma unroll 16
            for (int k = 0; k < DM; k++)
                acc = fmaf(sf[k], wr[k], acc);
            int idx = bcand[tid];
            sval[cbase + tid] = acc + benc[idx];
            sidx[cbase + tid] = idx;
        }
    }
    __syncthreads();

    if (tid < TOPC) {
        float v = sval[tid];
        int myi = sidx[tid];
        int rank = 0;
        #pragma unroll 8
        for (int j = 0; j < TOPC; j++) {
            float vj = sval[j];
            rank += (vj > v) || (vj == v && sidx[j] < myi);
        }
        if (rank < TOPK) {
            g_tki[row * TOPK + rank] = myi;
            g_tkv[row * TOPK + rank] = v;
            codes[(size_t)row * NF + myi] = v;
        }
    }
}

// ============================================================
// sparse decode
// ============================================================
__global__ __launch_bounds__(256)
void decode_kernel(const float* __restrict__ Dm, float* __restrict__ recon) {
    __shared__ int   sidx[TOPK];
    __shared__ float sval[TOPK];
    const int row = blockIdx.x;
    const int tid = threadIdx.x;
    if (tid < TOPK) {
        sidx[tid] = g_tki[row * TOPK + tid];
        sval[tid] = g_tkv[row * TOPK + tid];
    }
    __syncthreads();
    const int c0 = tid, c1 = tid + 256, c2 = tid + 512;
    float a0 = 0.f, a1 = 0.f, a2 = 0.f;
#pragma unroll 4
    for (int k = 0; k < TOPK; k++) {
        const float* dr = Dm + (size_t)sidx[k] * DM;
        float v = sval[k];
        a0 += v * dr[c0]; a1 += v * dr[c1]; a2 += v * dr[c2];
    }
    float* r = recon + (size_t)row * DM;
    r[c0] = a0; r[c1] = a1; r[c2] = a2;
}

// ============================================================
// launch
// ============================================================
extern "C" void kernel_launch(void* const* d_in, const int* in_sizes, int n_in,
                              void* d_out, int out_size) {
    const float* x    = (const float*)d_in[0];
    const float* Wenc = (const float*)d_in[1];
    const float* benc = (const float*)d_in[2];
    const float* Dm   = (const float*)d_in[3];

    float* out   = (float*)d_out;
    float* recon = out;
    float* codes = out + (size_t)M_ROWS * DM;
    float* pre   = codes + (size_t)M_ROWS * NF;

    cudaFuncSetAttribute(gemm_mma_kernel,
                         cudaFuncAttributeMaxDynamicSharedMemorySize, GEMM_SMEM);
    cudaFuncSetAttribute(topc_kernel,
                         cudaFuncAttributeMaxDynamicSharedMemorySize,
                         NF * (int)sizeof(unsigned));
    cudaFuncSetAttribute(rescore_kernel,
                         cudaFuncAttributeMaxDynamicSharedMemorySize, RS_SMEM);

    // 1) convert inputs to fp16 (single pass)
    convert_x_kernel<<<(M_ROWS * KDIM / 4 + 255) / 256, 256>>>(x);
    convert_w_kernel<<<(NF * KDIM / 4 + 255) / 256, 256>>>(Wenc);
    // 2) zero codes
    zero_kernel<<<16384, 256>>>((float4*)codes, (size_t)M_ROWS * NF / 4);
    // 3) fp16 tensor-core encode GEMM -> pre (+bias)
    {
        dim3 grid(M_ROWS / BM, NF / BN);
        gemm_mma_kernel<<<grid, 256, GEMM_SMEM>>>(benc, pre);
    }
    // 4) approx top-128 candidates
    topc_kernel<<<M_ROWS, 256, NF * sizeof(unsigned)>>>(pre);
    // 5) exact rescore -> top-64, scatter into codes
    rescore_kernel<<<M_ROWS, 256, RS_SMEM>>>(x, Wenc, benc, codes);
    // 6) sparse decode
    decode_kernel<<<M_ROWS, 256>>>(Dm, recon);
}

// round 8
// speedup vs baseline: 1.8126x; 1.3825x over previous
#include <cuda_runtime.h>
#include <cuda_fp16.h>
#include <stdint.h>

#define M_ROWS   8192
#define DM       768
#define NF       16384
#define TOPK     64
#define TOPC     128
#define KDIM     768

// ---------------- scratch (__device__ globals; no allocs) ----------------
__device__ __align__(256) __half g_A[M_ROWS * KDIM];   // 12.6 MB
__device__ __align__(256) __half g_B[NF     * KDIM];   // 25.2 MB

// ---------------- helpers ----------------
__device__ __forceinline__ uint32_t smem_u32(const void* p) {
    uint32_t a;
    asm("{ .reg .u64 t; cvta.to.shared.u64 t, %1; cvt.u32.u64 %0, t; }" : "=r"(a) : "l"(p));
    return a;
}
__device__ __forceinline__ void cp_async16(uint32_t dst, const void* src) {
    asm volatile("cp.async.cg.shared.global [%0], [%1], 16;" :: "r"(dst), "l"(src));
}
#define CP_COMMIT() asm volatile("cp.async.commit_group;" ::: "memory")
#define CP_WAIT(n)  asm volatile("cp.async.wait_group %0;" :: "n"(n) : "memory")

__device__ __forceinline__ void mma16816(float* c,
                                         uint32_t a0, uint32_t a1, uint32_t a2, uint32_t a3,
                                         uint32_t b0, uint32_t b1) {
    asm volatile("mma.sync.aligned.m16n8k16.row.col.f32.f16.f16.f32 "
        "{%0,%1,%2,%3}, {%4,%5,%6,%7}, {%8,%9}, {%0,%1,%2,%3};"
        : "+f"(c[0]), "+f"(c[1]), "+f"(c[2]), "+f"(c[3])
        : "r"(a0), "r"(a1), "r"(a2), "r"(a3), "r"(b0), "r"(b1));
}

// ============================================================
// convert: fp32 -> fp16, vectorized x4
// ============================================================
__global__ void convert_x_kernel(const float* __restrict__ x) {
    int i = blockIdx.x * blockDim.x + threadIdx.x;
    if (i >= M_ROWS * KDIM / 4) return;
    float4 v = ((const float4*)x)[i];
    ((__half2*)g_A)[i * 2]     = __floats2half2_rn(v.x, v.y);
    ((__half2*)g_A)[i * 2 + 1] = __floats2half2_rn(v.z, v.w);
}
__global__ void convert_w_kernel(const float* __restrict__ w) {
    int i = blockIdx.x * blockDim.x + threadIdx.x;
    if (i >= NF * KDIM / 4) return;
    float4 v = ((const float4*)w)[i];
    ((__half2*)g_B)[i * 2]     = __floats2half2_rn(v.x, v.y);
    ((__half2*)g_B)[i * 2 + 1] = __floats2half2_rn(v.z, v.w);
}

// ============================================================
// zero codes
// ============================================================
__global__ void zero_kernel(float4* __restrict__ p, size_t n4) {
    size_t i = (size_t)blockIdx.x * blockDim.x + threadIdx.x;
    size_t stride = (size_t)gridDim.x * blockDim.x;
    float4 z = make_float4(0.f, 0.f, 0.f, 0.f);
    for (; i < n4; i += stride) p[i] = z;
}

// ============================================================
// mma.sync fp16 GEMM, watertight 4-stage pipeline:
//   issue(kb+3); commit; wait_group(3); sync; compute(kb); sync
// One commit per iteration -> after wait(3) group kb complete.
// Buffer (kb+3)%4 == (kb-1)%4 reused only after iteration
// kb-1's trailing barrier. Provably quiescent.
// ============================================================
#define BM 128
#define BN 128
#define BK 32
#define STAGES 4
#define ROWB 80                        // 64B data (32 fp16) + 16B pad
#define STG (256 * ROWB)               // 20480 B
#define GEMM_SMEM (STAGES * STG)       // 81920 B
#define KITERS (KDIM / BK)             // 24

__global__ __launch_bounds__(256, 2)
void gemm_mma_kernel(const float* __restrict__ bias, float* __restrict__ pre) {
    extern __shared__ char sm[];
    const uint32_t sb = smem_u32(sm);
    const int tid = threadIdx.x;
    const int wid = tid >> 5;
    const int lane = tid & 31;
    const int g   = lane >> 2;
    const int tig = lane & 3;
    const int bm = blockIdx.x * BM;
    const int bn = blockIdx.y * BN;
    const int wm = (wid >> 2) * 64;
    const int wn = (wid & 3) * 32;

    const __half* Ag = g_A + (size_t)bm * KDIM;
    const __half* Bg = g_B + (size_t)bn * KDIM;

    float acc[4][4][4];
#pragma unroll
    for (int mi = 0; mi < 4; mi++)
#pragma unroll
        for (int ni = 0; ni < 4; ni++)
#pragma unroll
            for (int q = 0; q < 4; q++) acc[mi][ni][q] = 0.f;

    const int lr0 = tid >> 2;
    const int lr1 = (tid + 256) >> 2;
    const int lc  = tid & 3;

    auto issue = [&](int s) {
        const uint32_t base = sb + (s % STAGES) * STG;
        const size_t k0 = (size_t)s * BK;
        cp_async16(base + lr0 * ROWB + lc * 16, Ag + (size_t)lr0 * KDIM + k0 + lc * 8);
        cp_async16(base + lr1 * ROWB + lc * 16, Ag + (size_t)lr1 * KDIM + k0 + lc * 8);
        const uint32_t bb = base + 128 * ROWB;
        cp_async16(bb + lr0 * ROWB + lc * 16, Bg + (size_t)lr0 * KDIM + k0 + lc * 8);
        cp_async16(bb + lr1 * ROWB + lc * 16, Bg + (size_t)lr1 * KDIM + k0 + lc * 8);
    };

    issue(0); CP_COMMIT();
    issue(1); CP_COMMIT();
    issue(2); CP_COMMIT();

    for (int kb = 0; kb < KITERS; kb++) {
        if (kb + 3 < KITERS) issue(kb + 3);
        CP_COMMIT();                     // one group per iteration
        CP_WAIT(3);                      // group kb complete
        __syncthreads();

        const char* Abuf = sm + (kb % STAGES) * STG;
        const char* Bbuf = Abuf + 128 * ROWB;
#pragma unroll
        for (int kk = 0; kk < 2; kk++) {
            uint32_t bfr[4][2];
#pragma unroll
            for (int ni = 0; ni < 4; ni++) {
                const char* bp = Bbuf + (wn + ni * 8 + g) * ROWB + kk * 32 + tig * 4;
                bfr[ni][0] = *(const uint32_t*)bp;
                bfr[ni][1] = *(const uint32_t*)(bp + 16);
            }
#pragma unroll
            for (int mi = 0; mi < 4; mi++) {
                const char* ap0 = Abuf + (wm + mi * 16 + g) * ROWB + kk * 32 + tig * 4;
                const char* ap1 = ap0 + 8 * ROWB;
                uint32_t a0 = *(const uint32_t*)ap0;
                uint32_t a1 = *(const uint32_t*)ap1;
                uint32_t a2 = *(const uint32_t*)(ap0 + 16);
                uint32_t a3 = *(const uint32_t*)(ap1 + 16);
#pragma unroll
                for (int ni = 0; ni < 4; ni++)
                    mma16816(acc[mi][ni], a0, a1, a2, a3, bfr[ni][0], bfr[ni][1]);
            }
        }
        __syncthreads();
    }

#pragma unroll
    for (int ni = 0; ni < 4; ni++) {
        const int col = bn + wn + ni * 8 + tig * 2;
        float2 bz = *(const float2*)(bias + col);
#pragma unroll
        for (int mi = 0; mi < 4; mi++) {
            const int r0 = bm + wm + mi * 16 + g;
            float2 v0, v1;
            v0.x = acc[mi][ni][0] + bz.x; v0.y = acc[mi][ni][1] + bz.y;
            v1.x = acc[mi][ni][2] + bz.x; v1.y = acc[mi][ni][3] + bz.y;
            *(float2*)(pre + (size_t)r0 * NF + col)       = v0;
            *(float2*)(pre + (size_t)(r0 + 8) * NF + col) = v1;
        }
    }
}

// ============================================================
// FUSED post-GEMM kernel (one block per row):
//   phase 1: load pre row as ordered keys + x row
//   phase 2: radix top-128 select, per-warp histograms
//   phase 3: collect candidates
//   phase 4: exact fp32 rescore (ascending-k fmaf chain, +bias),
//            128 threads = 128 candidates, W via float4 LDG (L2)
//   phase 5: rank among 128 (idx tiebreak), scatter into codes
//   phase 6: sparse decode from smem tki/tkv
// ============================================================
#define OFF_SU    0
#define OFF_XS    65536
#define OFF_WH    (OFF_XS + DM * 4)            // 68608, 8 x 256 u32
#define OFF_SVAL  (OFF_WH + 8 * 256 * 4)       // 76800
#define OFF_SIDX  (OFF_SVAL + TOPC * 4)        // 77312
#define OFF_CIDX  (OFF_SIDX + TOPC * 4)        // 77824
#define OFF_TKI   (OFF_CIDX + TOPC * 4)        // 78336
#define OFF_TKV   (OFF_TKI + TOPK * 4)         // 78592
#define FUSE_SMEM (OFF_TKV + TOPK * 4)         // 78848

__global__ __launch_bounds__(256, 2)
void postgemm_kernel(const float* __restrict__ pre,
                     const float* __restrict__ x,
                     const float* __restrict__ Wenc,
                     const float* __restrict__ benc,
                     const float* __restrict__ Dm,
                     float* __restrict__ codes,
                     float* __restrict__ recon) {
    extern __shared__ char smraw[];
    unsigned* su    = (unsigned*)(smraw + OFF_SU);
    float*    xs    = (float*)   (smraw + OFF_XS);
    unsigned* whist = (unsigned*)(smraw + OFF_WH);
    float*    sval  = (float*)   (smraw + OFF_SVAL);
    int*      sidx  = (int*)     (smraw + OFF_SIDX);
    int*      cidx  = (int*)     (smraw + OFF_CIDX);
    int*      stki  = (int*)     (smraw + OFF_TKI);
    float*    stkv  = (float*)   (smraw + OFF_TKV);
    __shared__ unsigned s_prefix, s_want, s_cnt;

    const int row = blockIdx.x;
    const int tid = threadIdx.x;
    const int wid = tid >> 5;
    const float* p = pre + (size_t)row * NF;

    // phase 1: keys + x row
    for (int i = tid; i < NF; i += 256) {
        unsigned b = __float_as_uint(p[i]);
        su[i] = (b & 0x80000000u) ? ~b : (b | 0x80000000u);
    }
    for (int i = tid; i < DM; i += 256) xs[i] = x[(size_t)row * DM + i];
    if (tid == 0) { s_prefix = 0u; s_want = TOPC; s_cnt = 0u; }
    __syncthreads();

    // phase 2: 4-pass radix select with per-warp histograms
    unsigned* myh = whist + (wid << 8);
#pragma unroll
    for (int shift = 24; shift >= 0; shift -= 8) {
#pragma unroll
        for (int h = 0; h < 8; h++) whist[h * 256 + tid] = 0u;
        __syncthreads();
        unsigned pref = s_prefix;
        for (int i = tid; i < NF; i += 256) {
            unsigned u = su[i];
            bool match = (shift == 24) || ((u >> (shift + 8)) == pref);
            if (match) atomicAdd(&myh[(u >> shift) & 255u], 1u);
        }
        __syncthreads();
        unsigned tot = 0;
#pragma unroll
        for (int h = 0; h < 8; h++) tot += whist[h * 256 + tid];
        whist[tid] = tot;
        __syncthreads();
        if (tid == 0) {
            unsigned want = s_want, cum = 0;
            for (int b = 255; b >= 0; b--) {
                unsigned c = whist[b];
                if (cum + c >= want) { s_prefix = (pref << 8) | (unsigned)b; s_want = want - cum; break; }
                cum += c;
            }
        }
        __syncthreads();
    }

    // phase 3: collect 128 candidates (keys >= pivot)
    const unsigned pivot = s_prefix;
    for (int i = tid; i < NF; i += 256) {
        if (su[i] >= pivot) {
            unsigned slot = atomicAdd(&s_cnt, 1u);
            if (slot < TOPC) cidx[slot] = i;
        }
    }
    __syncthreads();

    // phase 4: exact fp32 rescore, ascending-k fmaf chain (+bias)
    if (tid < TOPC) {
        const int idx = cidx[tid];
        const float4* wr = (const float4*)(Wenc + (size_t)idx * DM);
        float acc = 0.f;
#pragma unroll 4
        for (int q = 0; q < DM / 4; q++) {
            float4 w = wr[q];
            acc = fmaf(xs[q * 4 + 0], w.x, acc);
            acc = fmaf(xs[q * 4 + 1], w.y, acc);
            acc = fmaf(xs[q * 4 + 2], w.z, acc);
            acc = fmaf(xs[q * 4 + 3], w.w, acc);
        }
        sval[tid] = acc + benc[idx];
        sidx[tid] = idx;
    }
    __syncthreads();

    // phase 5: rank + scatter
    if (tid < TOPC) {
        float v = sval[tid];
        int myi = sidx[tid];
        int rank = 0;
#pragma unroll 8
        for (int j = 0; j < TOPC; j++) {
            float vj = sval[j];
            rank += (vj > v) || (vj == v && sidx[j] < myi);
        }
        if (rank < TOPK) {
            stki[rank] = myi;
            stkv[rank] = v;
            codes[(size_t)row * NF + myi] = v;
        }
    }
    __syncthreads();

    // phase 6: sparse decode (rank order, matches prior rounds)
    {
        const int c0 = tid, c1 = tid + 256, c2 = tid + 512;
        float a0 = 0.f, a1 = 0.f, a2 = 0.f;
#pragma unroll 4
        for (int k = 0; k < TOPK; k++) {
            const float* dr = Dm + (size_t)stki[k] * DM;
            float v = stkv[k];
            a0 += v * dr[c0]; a1 += v * dr[c1]; a2 += v * dr[c2];
        }
        float* r = recon + (size_t)row * DM;
        r[c0] = a0; r[c1] = a1; r[c2] = a2;
    }
}

// ============================================================
// launch
// ============================================================
extern "C" void kernel_launch(void* const* d_in, const int* in_sizes, int n_in,
                              void* d_out, int out_size) {
    const float* x    = (const float*)d_in[0];
    const float* Wenc = (const float*)d_in[1];
    const float* benc = (const float*)d_in[2];
    const float* Dm   = (const float*)d_in[3];

    float* out   = (float*)d_out;
    float* recon = out;
    float* codes = out + (size_t)M_ROWS * DM;
    float* pre   = codes + (size_t)M_ROWS * NF;

    cudaFuncSetAttribute(gemm_mma_kernel,
                         cudaFuncAttributeMaxDynamicSharedMemorySize, GEMM_SMEM);
    cudaFuncSetAttribute(postgemm_kernel,
                         cudaFuncAttributeMaxDynamicSharedMemorySize, FUSE_SMEM);

    convert_x_kernel<<<(M_ROWS * KDIM / 4 + 255) / 256, 256>>>(x);
    convert_w_kernel<<<(NF * KDIM / 4 + 255) / 256, 256>>>(Wenc);
    zero_kernel<<<16384, 256>>>((float4*)codes, (size_t)M_ROWS * NF / 4);
    {
        dim3 grid(M_ROWS / BM, NF / BN);
        gemm_mma_kernel<<<grid, 256, GEMM_SMEM>>>(benc, pre);
    }
    postgemm_kernel<<<M_ROWS, 256, FUSE_SMEM>>>(pre, x, Wenc, benc, Dm,
                                                codes, recon);
}

// round 9
// speedup vs baseline: 1.9716x; 1.0878x over previous
#include <cuda_runtime.h>
#include <cuda_fp16.h>
#include <stdint.h>

#define M_ROWS   8192
#define DM       768
#define NF       16384
#define TOPK     64
#define TOPC     128
#define KDIM     768

// ---------------- scratch (__device__ globals; no allocs) ----------------
__device__ __align__(256) __half g_A[M_ROWS * KDIM];   // 12.6 MB
__device__ __align__(256) __half g_B[NF     * KDIM];   // 25.2 MB

// ---------------- helpers ----------------
__device__ __forceinline__ uint32_t smem_u32(const void* p) {
    uint32_t a;
    asm("{ .reg .u64 t; cvta.to.shared.u64 t, %1; cvt.u32.u64 %0, t; }" : "=r"(a) : "l"(p));
    return a;
}
__device__ __forceinline__ void cp_async16(uint32_t dst, const void* src) {
    asm volatile("cp.async.cg.shared.global [%0], [%1], 16;" :: "r"(dst), "l"(src));
}
#define CP_COMMIT() asm volatile("cp.async.commit_group;" ::: "memory")
#define CP_WAIT(n)  asm volatile("cp.async.wait_group %0;" :: "n"(n) : "memory")

__device__ __forceinline__ void mma16816(float* c,
                                         uint32_t a0, uint32_t a1, uint32_t a2, uint32_t a3,
                                         uint32_t b0, uint32_t b1) {
    asm volatile("mma.sync.aligned.m16n8k16.row.col.f32.f16.f16.f32 "
        "{%0,%1,%2,%3}, {%4,%5,%6,%7}, {%8,%9}, {%0,%1,%2,%3};"
        : "+f"(c[0]), "+f"(c[1]), "+f"(c[2]), "+f"(c[3])
        : "r"(a0), "r"(a1), "r"(a2), "r"(a3), "r"(b0), "r"(b1));
}

// ============================================================
// convert: fp32 -> fp16, vectorized x4
// ============================================================
__global__ void convert_x_kernel(const float* __restrict__ x) {
    int i = blockIdx.x * blockDim.x + threadIdx.x;
    if (i >= M_ROWS * KDIM / 4) return;
    float4 v = ((const float4*)x)[i];
    ((__half2*)g_A)[i * 2]     = __floats2half2_rn(v.x, v.y);
    ((__half2*)g_A)[i * 2 + 1] = __floats2half2_rn(v.z, v.w);
}
__global__ void convert_w_kernel(const float* __restrict__ w) {
    int i = blockIdx.x * blockDim.x + threadIdx.x;
    if (i >= NF * KDIM / 4) return;
    float4 v = ((const float4*)w)[i];
    ((__half2*)g_B)[i * 2]     = __floats2half2_rn(v.x, v.y);
    ((__half2*)g_B)[i * 2 + 1] = __floats2half2_rn(v.z, v.w);
}

// ============================================================
// mma.sync fp16 GEMM, watertight 4-stage pipeline (validated R8)
// ============================================================
#define BM 128
#define BN 128
#define BK 32
#define STAGES 4
#define ROWB 80
#define STG (256 * ROWB)
#define GEMM_SMEM (STAGES * STG)       // 81920 B
#define KITERS (KDIM / BK)             // 24

__global__ __launch_bounds__(256, 2)
void gemm_mma_kernel(const float* __restrict__ bias, float* __restrict__ pre) {
    extern __shared__ char sm[];
    const uint32_t sb = smem_u32(sm);
    const int tid = threadIdx.x;
    const int wid = tid >> 5;
    const int lane = tid & 31;
    const int g   = lane >> 2;
    const int tig = lane & 3;
    const int bm = blockIdx.x * BM;
    const int bn = blockIdx.y * BN;
    const int wm = (wid >> 2) * 64;
    const int wn = (wid & 3) * 32;

    const __half* Ag = g_A + (size_t)bm * KDIM;
    const __half* Bg = g_B + (size_t)bn * KDIM;

    float acc[4][4][4];
#pragma unroll
    for (int mi = 0; mi < 4; mi++)
#pragma unroll
        for (int ni = 0; ni < 4; ni++)
#pragma unroll
            for (int q = 0; q < 4; q++) acc[mi][ni][q] = 0.f;

    const int lr0 = tid >> 2;
    const int lr1 = (tid + 256) >> 2;
    const int lc  = tid & 3;

    auto issue = [&](int s) {
        const uint32_t base = sb + (s % STAGES) * STG;
        const size_t k0 = (size_t)s * BK;
        cp_async16(base + lr0 * ROWB + lc * 16, Ag + (size_t)lr0 * KDIM + k0 + lc * 8);
        cp_async16(base + lr1 * ROWB + lc * 16, Ag + (size_t)lr1 * KDIM + k0 + lc * 8);
        const uint32_t bb = base + 128 * ROWB;
        cp_async16(bb + lr0 * ROWB + lc * 16, Bg + (size_t)lr0 * KDIM + k0 + lc * 8);
        cp_async16(bb + lr1 * ROWB + lc * 16, Bg + (size_t)lr1 * KDIM + k0 + lc * 8);
    };

    issue(0); CP_COMMIT();
    issue(1); CP_COMMIT();
    issue(2); CP_COMMIT();

    for (int kb = 0; kb < KITERS; kb++) {
        if (kb + 3 < KITERS) issue(kb + 3);
        CP_COMMIT();
        CP_WAIT(3);
        __syncthreads();

        const char* Abuf = sm + (kb % STAGES) * STG;
        const char* Bbuf = Abuf + 128 * ROWB;
#pragma unroll
        for (int kk = 0; kk < 2; kk++) {
            uint32_t bfr[4][2];
#pragma unroll
            for (int ni = 0; ni < 4; ni++) {
                const char* bp = Bbuf + (wn + ni * 8 + g) * ROWB + kk * 32 + tig * 4;
                bfr[ni][0] = *(const uint32_t*)bp;
                bfr[ni][1] = *(const uint32_t*)(bp + 16);
            }
#pragma unroll
            for (int mi = 0; mi < 4; mi++) {
                const char* ap0 = Abuf + (wm + mi * 16 + g) * ROWB + kk * 32 + tig * 4;
                const char* ap1 = ap0 + 8 * ROWB;
                uint32_t a0 = *(const uint32_t*)ap0;
                uint32_t a1 = *(const uint32_t*)ap1;
                uint32_t a2 = *(const uint32_t*)(ap0 + 16);
                uint32_t a3 = *(const uint32_t*)(ap1 + 16);
#pragma unroll
                for (int ni = 0; ni < 4; ni++)
                    mma16816(acc[mi][ni], a0, a1, a2, a3, bfr[ni][0], bfr[ni][1]);
            }
        }
        __syncthreads();
    }

#pragma unroll
    for (int ni = 0; ni < 4; ni++) {
        const int col = bn + wn + ni * 8 + tig * 2;
        float2 bz = *(const float2*)(bias + col);
#pragma unroll
        for (int mi = 0; mi < 4; mi++) {
            const int r0 = bm + wm + mi * 16 + g;
            float2 v0, v1;
            v0.x = acc[mi][ni][0] + bz.x; v0.y = acc[mi][ni][1] + bz.y;
            v1.x = acc[mi][ni][2] + bz.x; v1.y = acc[mi][ni][3] + bz.y;
            *(float2*)(pre + (size_t)r0 * NF + col)       = v0;
            *(float2*)(pre + (size_t)(r0 + 8) * NF + col) = v1;
        }
    }
}

// ============================================================
// FUSED post-GEMM (one block/row): radix top-128 (parallel
// pivot scan) -> exact fp32 rescore -> rank -> codes row write
// (smem-staged, fully coalesced) -> sparse decode.
// ============================================================
#define OFF_SU    0
#define OFF_XS    65536
#define OFF_WH    (OFF_XS + DM * 4)            // 8 x 256 u32 (also scan scratch)
#define OFF_SVAL  (OFF_WH + 8 * 256 * 4)
#define OFF_SIDX  (OFF_SVAL + TOPC * 4)
#define OFF_CIDX  (OFF_SIDX + TOPC * 4)
#define OFF_TKI   (OFF_CIDX + TOPC * 4)
#define OFF_TKV   (OFF_TKI + TOPK * 4)
#define FUSE_SMEM (OFF_TKV + TOPK * 4)         // 78848

__global__ __launch_bounds__(256, 2)
void postgemm_kernel(const float* __restrict__ pre,
                     const float* __restrict__ x,
                     const float* __restrict__ Wenc,
                     const float* __restrict__ benc,
                     const float* __restrict__ Dm,
                     float* __restrict__ codes,
                     float* __restrict__ recon) {
    extern __shared__ char smraw[];
    unsigned* su    = (unsigned*)(smraw + OFF_SU);
    float*    xs    = (float*)   (smraw + OFF_XS);
    unsigned* whist = (unsigned*)(smraw + OFF_WH);
    unsigned* scin  = whist + 256;             // scan input (reversed bins)
    unsigned* wsum  = whist + 512;             // 8 warp partials
    float*    sval  = (float*)   (smraw + OFF_SVAL);
    int*      sidx  = (int*)     (smraw + OFF_SIDX);
    int*      cidx  = (int*)     (smraw + OFF_CIDX);
    int*      stki  = (int*)     (smraw + OFF_TKI);
    float*    stkv  = (float*)   (smraw + OFF_TKV);
    __shared__ unsigned s_prefix, s_want, s_cnt;

    const int row = blockIdx.x;
    const int tid = threadIdx.x;
    const int wid = tid >> 5;
    const int lane = tid & 31;
    const float* p = pre + (size_t)row * NF;

    // phase 1: keys + x row
    for (int i = tid; i < NF; i += 256) {
        unsigned b = __float_as_uint(p[i]);
        su[i] = (b & 0x80000000u) ? ~b : (b | 0x80000000u);
    }
    for (int i = tid; i < DM; i += 256) xs[i] = x[(size_t)row * DM + i];
    if (tid == 0) { s_prefix = 0u; s_want = TOPC; s_cnt = 0u; }
    __syncthreads();

    // phase 2: 4-pass radix select, per-warp hist + parallel pivot scan
    unsigned* myh = whist + (wid << 8);
#pragma unroll
    for (int shift = 24; shift >= 0; shift -= 8) {
#pragma unroll
        for (int h = 0; h < 8; h++) whist[h * 256 + tid] = 0u;
        __syncthreads();
        const unsigned pref = s_prefix;
        const unsigned want = s_want;
        for (int i = tid; i < NF; i += 256) {
            unsigned u = su[i];
            bool match = (shift == 24) || ((u >> (shift + 8)) == pref);
            if (match) atomicAdd(&myh[(u >> shift) & 255u], 1u);
        }
        __syncthreads();
        unsigned tot = 0;
#pragma unroll
        for (int h = 0; h < 8; h++) tot += whist[h * 256 + tid];
        __syncthreads();                 // all hist reads done before scan scratch writes
        scin[255 - tid] = tot;           // reversed: ascending j = descending bin
        __syncthreads();
        // block inclusive scan over scin[0..255]
        unsigned v = scin[tid];
#pragma unroll
        for (int o = 1; o < 32; o <<= 1) {
            unsigned n = __shfl_up_sync(0xffffffffu, v, o);
            if (lane >= o) v += n;
        }
        if (lane == 31) wsum[wid] = v;
        __syncthreads();
        if (wid == 0 && lane < 8) {
            unsigned w = wsum[lane];
#pragma unroll
            for (int o = 1; o < 8; o <<= 1) {
                unsigned n = __shfl_up_sync(0x000000ffu, w, o);
                if (lane >= o) w += n;
            }
            wsum[lane] = w;
        }
        __syncthreads();
        unsigned incl = v + (wid > 0 ? wsum[wid - 1] : 0u);
        unsigned excl = incl - scin[tid];
        // bin for this thread (reversed): 255 - tid
        if (excl < want && want <= incl) {
            s_prefix = (pref << 8) | (unsigned)(255 - tid);
            s_want = want - excl;
        }
        __syncthreads();
    }

    // phase 3: collect TOPC candidates (keys >= pivot)
    const unsigned pivot = s_prefix;
    for (int i = tid; i < NF; i += 256) {
        if (su[i] >= pivot) {
            unsigned slot = atomicAdd(&s_cnt, 1u);
            if (slot < TOPC) cidx[slot] = i;
        }
    }
    __syncthreads();

    // phase 4a: zero su (reused as codes-row staging)
    {
        uint4 z = make_uint4(0u, 0u, 0u, 0u);
        uint4* su4 = (uint4*)su;
        for (int i = tid; i < NF / 4; i += 256) su4[i] = z;
    }
    // phase 4b: exact fp32 rescore, ascending-k fmaf chain (+bias)
    if (tid < TOPC) {
        const int idx = cidx[tid];
        const float4* wr = (const float4*)(Wenc + (size_t)idx * DM);
        float acc = 0.f;
#pragma unroll 4
        for (int q = 0; q < DM / 4; q++) {
            float4 w = wr[q];
            acc = fmaf(xs[q * 4 + 0], w.x, acc);
            acc = fmaf(xs[q * 4 + 1], w.y, acc);
            acc = fmaf(xs[q * 4 + 2], w.z, acc);
            acc = fmaf(xs[q * 4 + 3], w.w, acc);
        }
        sval[tid] = acc + benc[idx];
        sidx[tid] = idx;
    }
    __syncthreads();

    // phase 5: rank + stage top-64 into su (as codes row)
    if (tid < TOPC) {
        float v = sval[tid];
        int myi = sidx[tid];
        int rank = 0;
#pragma unroll 8
        for (int j = 0; j < TOPC; j++) {
            float vj = sval[j];
            rank += (vj > v) || (vj == v && sidx[j] < myi);
        }
        if (rank < TOPK) {
            stki[rank] = myi;
            stkv[rank] = v;
            su[myi] = __float_as_uint(v);
        }
    }
    __syncthreads();

    // phase 6a: stream codes row out (coalesced float4)
    {
        float4* crow = (float4*)(codes + (size_t)row * NF);
        const float4* su4 = (const float4*)su;
        for (int i = tid; i < NF / 4; i += 256) crow[i] = su4[i];
    }
    // phase 6b: sparse decode
    {
        const int c0 = tid, c1 = tid + 256, c2 = tid + 512;
        float a0 = 0.f, a1 = 0.f, a2 = 0.f;
#pragma unroll 4
        for (int k = 0; k < TOPK; k++) {
            const float* dr = Dm + (size_t)stki[k] * DM;
            float v = stkv[k];
            a0 += v * dr[c0]; a1 += v * dr[c1]; a2 += v * dr[c2];
        }
        float* r = recon + (size_t)row * DM;
        r[c0] = a0; r[c1] = a1; r[c2] = a2;
    }
}

// ============================================================
// launch
// ============================================================
extern "C" void kernel_launch(void* const* d_in, const int* in_sizes, int n_in,
                              void* d_out, int out_size) {
    const float* x    = (const float*)d_in[0];
    const float* Wenc = (const float*)d_in[1];
    const float* benc = (const float*)d_in[2];
    const float* Dm   = (const float*)d_in[3];

    float* out   = (float*)d_out;
    float* recon = out;
    float* codes = out + (size_t)M_ROWS * DM;
    float* pre   = codes + (size_t)M_ROWS * NF;

    cudaFuncSetAttribute(gemm_mma_kernel,
                         cudaFuncAttributeMaxDynamicSharedMemorySize, GEMM_SMEM);
    cudaFuncSetAttribute(postgemm_kernel,
                         cudaFuncAttributeMaxDynamicSharedMemorySize, FUSE_SMEM);

    convert_x_kernel<<<(M_ROWS * KDIM / 4 + 255) / 256, 256>>>(x);
    convert_w_kernel<<<(NF * KDIM / 4 + 255) / 256, 256>>>(Wenc);
    {
        dim3 grid(M_ROWS / BM, NF / BN);
        gemm_mma_kernel<<<grid, 256, GEMM_SMEM>>>(benc, pre);
    }
    postgemm_kernel<<<M_ROWS, 256, FUSE_SMEM>>>(pre, x, Wenc, benc, Dm,
                                                codes, recon);
}